// round 2
// baseline (speedup 1.0000x reference)
#include <cuda_runtime.h>
#include <math.h>

#define NN 50000
#define NE 800000
#define NG 256
#define HD 128
#define BN_EPS 1e-5f

// ---------------- device scratch (no allocation allowed) ----------------
__device__ float g_agg[NN * HD];
__device__ float g_x[NN * HD];
__device__ float g_buf[NN * HD];
__device__ float g_enc0[NN * HD];
__device__ float g_enc1[NN * HD];
__device__ float g_stats[2 * HD];     // [0:128) sum, [128:256) sumsq
__device__ float g_scale[HD];
__device__ float g_shift[HD];
__device__ float g_hg[NG * 2 * HD];
__device__ float g_m1[NG * HD];
__device__ float g_m2[NG * HD];

// ---------------- zero kernels ----------------
__global__ void zero_agg_stats_kernel() {
    int i = blockIdx.x * blockDim.x + threadIdx.x;
    float4 z = make_float4(0.f, 0.f, 0.f, 0.f);
    if (i < NN * HD / 4) ((float4*)g_agg)[i] = z;
    if (i < (2 * HD) / 4) ((float4*)g_stats)[i] = z;
}

__global__ void zero_hg_kernel() {
    int i = blockIdx.x * blockDim.x + threadIdx.x;
    if (i < NG * 2 * HD / 4) ((float4*)g_hg)[i] = make_float4(0.f, 0.f, 0.f, 0.f);
}

// ---------------- edge aggregation: agg[dst] += h[src] ----------------
// one warp per edge, lane handles 4 consecutive floats (float4)
__global__ __launch_bounds__(256) void agg_kernel(
    const float* __restrict__ h, const int* __restrict__ src,
    const int* __restrict__ dst)
{
    long long gid = (long long)blockIdx.x * blockDim.x + threadIdx.x;
    int e = (int)(gid >> 5);
    int lane = (int)(gid & 31);
    if (e >= NE) return;
    int s = src[e];
    int d = dst[e];
    float4 v = ((const float4*)h)[(long long)s * 32 + lane];
    float* out = g_agg + (long long)d * HD + lane * 4;
    atomicAdd(out + 0, v.x);
    atomicAdd(out + 1, v.y);
    atomicAdd(out + 2, v.z);
    atomicAdd(out + 3, v.w);
}

// ---------------- GEMM1: x = ((1+eps)*h + agg) @ W + b, fused BN stats ----
// BM=64, BN=128, K=128 in two 64-chunks. 256 threads, 4x8 register tile.
__global__ __launch_bounds__(256) void gemm_stats_kernel(
    const float* __restrict__ hin, const float* __restrict__ agg,
    const float* __restrict__ W, const float* __restrict__ bias,
    const float* __restrict__ eps_ptr, float* __restrict__ out)
{
    __shared__ float a_s[64 * 64];    // [k][row]
    __shared__ float w_s[64 * 128];   // [k][col]
    int tid = threadIdx.x;
    int tr = tid >> 4;      // 0..15 -> rows 4*tr..
    int tc = tid & 15;      // 0..15 -> cols 8*tc..
    int row0 = blockIdx.x * 64;
    float eps1 = 1.0f + eps_ptr[0];

    float acc[4][8];
#pragma unroll
    for (int i = 0; i < 4; i++)
#pragma unroll
        for (int j = 0; j < 8; j++) acc[i][j] = 0.f;

    for (int kc = 0; kc < 2; kc++) {
        int kbase = kc * 64;
        // stage A (transposed): 64 rows x 64 k
        {
            int r = tid & 63;
            int q0 = tid >> 6;  // 0..3
            int grow = row0 + r;
#pragma unroll
            for (int p = 0; p < 4; p++) {
                int k = (q0 + p * 4) * 4;  // 0..60 step: covers 64 k in float4s
                float4 v = make_float4(0.f, 0.f, 0.f, 0.f);
                if (grow < NN) {
                    float4 hv = *(const float4*)&hin[(long long)grow * HD + kbase + k];
                    float4 av = *(const float4*)&agg[(long long)grow * HD + kbase + k];
                    v.x = eps1 * hv.x + av.x;
                    v.y = eps1 * hv.y + av.y;
                    v.z = eps1 * hv.z + av.z;
                    v.w = eps1 * hv.w + av.w;
                }
                a_s[(k + 0) * 64 + r] = v.x;
                a_s[(k + 1) * 64 + r] = v.y;
                a_s[(k + 2) * 64 + r] = v.z;
                a_s[(k + 3) * 64 + r] = v.w;
            }
        }
        // stage W: 64 k x 128 cols
        {
#pragma unroll
            for (int p = 0; p < 8; p++) {
                int idx = tid + p * 256;   // 0..2047 float4s
                int k = idx >> 5;
                int q = idx & 31;
                *(float4*)&w_s[k * 128 + q * 4] =
                    *(const float4*)&W[(long long)(kbase + k) * HD + q * 4];
            }
        }
        __syncthreads();
#pragma unroll 8
        for (int k = 0; k < 64; k++) {
            float4 av = *(const float4*)(a_s + k * 64 + 4 * tr);
            float4 w0 = *(const float4*)(w_s + k * 128 + 8 * tc);
            float4 w1 = *(const float4*)(w_s + k * 128 + 8 * tc + 4);
            float ar[4] = {av.x, av.y, av.z, av.w};
            float wr[8] = {w0.x, w0.y, w0.z, w0.w, w1.x, w1.y, w1.z, w1.w};
#pragma unroll
            for (int i = 0; i < 4; i++)
#pragma unroll
                for (int j = 0; j < 8; j++)
                    acc[i][j] = fmaf(ar[i], wr[j], acc[i][j]);
        }
        __syncthreads();
    }

    // epilogue: bias, store, BN stats
    float* s_sum = a_s;         // reuse smem (256 floats)
    float* s_sq = a_s + HD;
    if (tid < 64) ((float4*)s_sum)[tid] = make_float4(0.f, 0.f, 0.f, 0.f);
    __syncthreads();

    float colsum[8], colsq[8];
#pragma unroll
    for (int j = 0; j < 8; j++) { colsum[j] = 0.f; colsq[j] = 0.f; }
#pragma unroll
    for (int i = 0; i < 4; i++) {
        int grow = row0 + 4 * tr + i;
        if (grow < NN) {
            float vals[8];
#pragma unroll
            for (int j = 0; j < 8; j++) {
                float v = acc[i][j] + bias[8 * tc + j];
                vals[j] = v;
                colsum[j] += v;
                colsq[j] += v * v;
            }
            *(float4*)&out[(long long)grow * HD + 8 * tc] =
                make_float4(vals[0], vals[1], vals[2], vals[3]);
            *(float4*)&out[(long long)grow * HD + 8 * tc + 4] =
                make_float4(vals[4], vals[5], vals[6], vals[7]);
        }
    }
#pragma unroll
    for (int j = 0; j < 8; j++) {
        atomicAdd(&s_sum[8 * tc + j], colsum[j]);
        atomicAdd(&s_sq[8 * tc + j], colsq[j]);
    }
    __syncthreads();
    if (tid < HD) {
        atomicAdd(&g_stats[tid], s_sum[tid]);
        atomicAdd(&g_stats[HD + tid], s_sq[tid]);
    }
}

// ---------------- finalize BN stats -> per-channel scale/shift ------------
__global__ void finalize_stats_kernel(const float* __restrict__ gamma,
                                      const float* __restrict__ beta)
{
    int c = threadIdx.x;
    const float inv = 1.0f / (float)NN;
    float mean = g_stats[c] * inv;
    float var = g_stats[HD + c] * inv - mean * mean;
    float sc = gamma[c] * rsqrtf(var + BN_EPS);
    g_scale[c] = sc;
    g_shift[c] = beta[c] - mean * sc;
}

// ---------------- GEMM2: out = relu?(relu(BN(x)) @ W + b) ----------------
__global__ __launch_bounds__(256) void gemm_bn_kernel(
    const float* __restrict__ xin, const float* __restrict__ W,
    const float* __restrict__ bias, float* __restrict__ out, int relu_out)
{
    __shared__ float a_s[64 * 64];
    __shared__ float w_s[64 * 128];
    int tid = threadIdx.x;
    int tr = tid >> 4;
    int tc = tid & 15;
    int row0 = blockIdx.x * 64;

    float acc[4][8];
#pragma unroll
    for (int i = 0; i < 4; i++)
#pragma unroll
        for (int j = 0; j < 8; j++) acc[i][j] = 0.f;

    for (int kc = 0; kc < 2; kc++) {
        int kbase = kc * 64;
        {
            int r = tid & 63;
            int q0 = tid >> 6;
            int grow = row0 + r;
#pragma unroll
            for (int p = 0; p < 4; p++) {
                int k = (q0 + p * 4) * 4;
                float4 v = make_float4(0.f, 0.f, 0.f, 0.f);
                if (grow < NN) {
                    float4 xv = *(const float4*)&xin[(long long)grow * HD + kbase + k];
                    v.x = fmaxf(xv.x * g_scale[kbase + k + 0] + g_shift[kbase + k + 0], 0.f);
                    v.y = fmaxf(xv.y * g_scale[kbase + k + 1] + g_shift[kbase + k + 1], 0.f);
                    v.z = fmaxf(xv.z * g_scale[kbase + k + 2] + g_shift[kbase + k + 2], 0.f);
                    v.w = fmaxf(xv.w * g_scale[kbase + k + 3] + g_shift[kbase + k + 3], 0.f);
                }
                a_s[(k + 0) * 64 + r] = v.x;
                a_s[(k + 1) * 64 + r] = v.y;
                a_s[(k + 2) * 64 + r] = v.z;
                a_s[(k + 3) * 64 + r] = v.w;
            }
        }
        {
#pragma unroll
            for (int p = 0; p < 8; p++) {
                int idx = tid + p * 256;
                int k = idx >> 5;
                int q = idx & 31;
                *(float4*)&w_s[k * 128 + q * 4] =
                    *(const float4*)&W[(long long)(kbase + k) * HD + q * 4];
            }
        }
        __syncthreads();
#pragma unroll 8
        for (int k = 0; k < 64; k++) {
            float4 av = *(const float4*)(a_s + k * 64 + 4 * tr);
            float4 w0 = *(const float4*)(w_s + k * 128 + 8 * tc);
            float4 w1 = *(const float4*)(w_s + k * 128 + 8 * tc + 4);
            float ar[4] = {av.x, av.y, av.z, av.w};
            float wr[8] = {w0.x, w0.y, w0.z, w0.w, w1.x, w1.y, w1.z, w1.w};
#pragma unroll
            for (int i = 0; i < 4; i++)
#pragma unroll
                for (int j = 0; j < 8; j++)
                    acc[i][j] = fmaf(ar[i], wr[j], acc[i][j]);
        }
        __syncthreads();
    }

#pragma unroll
    for (int i = 0; i < 4; i++) {
        int grow = row0 + 4 * tr + i;
        if (grow < NN) {
            float vals[8];
#pragma unroll
            for (int j = 0; j < 8; j++) {
                float v = acc[i][j] + bias[8 * tc + j];
                if (relu_out) v = fmaxf(v, 0.f);
                vals[j] = v;
            }
            *(float4*)&out[(long long)grow * HD + 8 * tc] =
                make_float4(vals[0], vals[1], vals[2], vals[3]);
            *(float4*)&out[(long long)grow * HD + 8 * tc + 4] =
                make_float4(vals[4], vals[5], vals[6], vals[7]);
        }
    }
}

// ---------------- per-graph readout (graph_ids sorted) --------------------
__global__ __launch_bounds__(256) void readout_kernel(const int* __restrict__ gids)
{
    int c = threadIdx.x;                 // 0..255 output column
    const float* h = (c < HD) ? g_enc0 : g_enc1;
    int cc = c & (HD - 1);
    int n0 = blockIdx.x * 128;
    int n1 = n0 + 128;
    if (n1 > NN) n1 = NN;
    int cur = gids[n0];
    float acc = 0.f;
    for (int n = n0; n < n1; n++) {
        int g = gids[n];
        if (g != cur) {
            atomicAdd(&g_hg[cur * 2 * HD + c], acc);
            acc = 0.f;
            cur = g;
        }
        acc += h[(long long)n * HD + cc];
    }
    atomicAdd(&g_hg[cur * 2 * HD + c], acc);
}

// ---------------- output MLP ----------------
__global__ void mlp1_kernel(const float* __restrict__ W, const float* __restrict__ b)
{
    __shared__ float row[2 * HD];
    int g = blockIdx.x, c = threadIdx.x;
    row[c] = g_hg[g * 2 * HD + c];
    row[c + HD] = g_hg[g * 2 * HD + c + HD];
    __syncthreads();
    float acc = b[c];
#pragma unroll 4
    for (int k = 0; k < 2 * HD; k++) acc = fmaf(row[k], W[k * HD + c], acc);
    g_m1[g * HD + c] = fmaxf(acc, 0.f);
}

__global__ void mlp2_kernel(const float* __restrict__ W, const float* __restrict__ b)
{
    __shared__ float row[HD];
    int g = blockIdx.x, c = threadIdx.x;
    row[c] = g_m1[g * HD + c];
    __syncthreads();
    float acc = b[c];
#pragma unroll 4
    for (int k = 0; k < HD; k++) acc = fmaf(row[k], W[k * HD + c], acc);
    g_m2[g * HD + c] = fmaxf(acc, 0.f);
}

__global__ void mlp3_kernel(const float* __restrict__ W, const float* __restrict__ b,
                            float* __restrict__ out)
{
    int g = threadIdx.x;
    if (g < NG) {
        float acc = b[0];
#pragma unroll 4
        for (int k = 0; k < HD; k++) acc = fmaf(g_m2[g * HD + k], W[k], acc);
        out[g] = acc;
    }
}

// ---------------- launch ----------------
extern "C" void kernel_launch(void* const* d_in, const int* in_sizes, int n_in,
                              void* d_out, int out_size)
{
    const float* feats = (const float*)d_in[0];
    const int* src = (const int*)d_in[1];
    const int* dst = (const int*)d_in[2];
    const int* gids = (const int*)d_in[3];
    // d_in[4] = n_graphs (always 256)
    const float* eps = (const float*)d_in[5];
    const float* Wa = (const float*)d_in[6];
    const float* ba = (const float*)d_in[7];
    const float* bng = (const float*)d_in[8];
    const float* bnb = (const float*)d_in[9];
    const float* Wb = (const float*)d_in[10];
    const float* bb = (const float*)d_in[11];
    const float* oW1 = (const float*)d_in[12];
    const float* ob1 = (const float*)d_in[13];
    const float* oW2 = (const float*)d_in[14];
    const float* ob2 = (const float*)d_in[15];
    const float* oW3 = (const float*)d_in[16];
    const float* ob3 = (const float*)d_in[17];
    float* out = (float*)d_out;

    float *aggp, *xp, *bufp, *e0p, *e1p;
    cudaGetSymbolAddress((void**)&aggp, g_agg);
    cudaGetSymbolAddress((void**)&xp, g_x);
    cudaGetSymbolAddress((void**)&bufp, g_buf);
    cudaGetSymbolAddress((void**)&e0p, g_enc0);
    cudaGetSymbolAddress((void**)&e1p, g_enc1);

    const int gemm_blocks = (NN + 63) / 64;          // 782
    const int agg_blocks = (NE * 32 + 255) / 256;    // 100000
    const int zero_blocks = (NN * HD / 4 + 255) / 256;

    for (int e = 0; e < 2; e++) {
        const int* se = src + e * NE;
        const int* de = dst + e * NE;
        float* enc = e ? e1p : e0p;
        const float* hin = feats;
        for (int l = 0; l < 2; l++) {
            int wl = e * 2 + l;
            zero_agg_stats_kernel<<<zero_blocks, 256>>>();
            agg_kernel<<<agg_blocks, 256>>>(hin, se, de);
            gemm_stats_kernel<<<gemm_blocks, 256>>>(
                hin, aggp, Wa + (long long)wl * HD * HD, ba + wl * HD, eps + wl, xp);
            finalize_stats_kernel<<<1, HD>>>(bng + wl * HD, bnb + wl * HD);
            float* o = (l == 0) ? bufp : enc;
            gemm_bn_kernel<<<gemm_blocks, 256>>>(
                xp, Wb + (long long)wl * HD * HD, bb + wl * HD, o, (l == 0) ? 1 : 0);
            hin = bufp;
        }
    }

    zero_hg_kernel<<<(NG * 2 * HD / 4 + 255) / 256, 256>>>();
    readout_kernel<<<(NN + 127) / 128, 256>>>(gids);
    mlp1_kernel<<<NG, HD>>>(oW1, ob1);
    mlp2_kernel<<<NG, HD>>>(oW2, ob2);
    mlp3_kernel<<<1, NG>>>(oW3, ob3, out);
}

// round 3
// speedup vs baseline: 1.3916x; 1.3916x over previous
#include <cuda_runtime.h>
#include <math.h>

#define NN 50000
#define NE 800000
#define NG 256
#define HD 128
#define BN_EPS 1e-5f

// ---------------- device scratch (no allocation allowed) ----------------
__device__ float g_agg[NN * HD];
__device__ float g_x[NN * HD];
__device__ float g_buf[NN * HD];
__device__ float g_enc0[NN * HD];
__device__ float g_enc1[NN * HD];
__device__ float g_stats[2 * HD];     // [0:128) sum, [128:256) sumsq
__device__ float g_scale[HD];
__device__ float g_shift[HD];
__device__ float g_hg[NG * 2 * HD];
__device__ float g_m1[NG * HD];
__device__ float g_m2[NG * HD];

// ---------------- zero kernels ----------------
__global__ void zero_agg_stats_kernel() {
    int i = blockIdx.x * blockDim.x + threadIdx.x;
    float4 z = make_float4(0.f, 0.f, 0.f, 0.f);
    if (i < NN * HD / 4) ((float4*)g_agg)[i] = z;
    if (i < (2 * HD) / 4) ((float4*)g_stats)[i] = z;
}

__global__ void zero_hg_kernel() {
    int i = blockIdx.x * blockDim.x + threadIdx.x;
    if (i < NG * 2 * HD / 4) ((float4*)g_hg)[i] = make_float4(0.f, 0.f, 0.f, 0.f);
}

// ---------------- edge aggregation: agg[dst] += h[src] ----------------
// one warp per edge; lane handles one float4; single v4 reduction per lane
__global__ __launch_bounds__(256) void agg_kernel(
    const float* __restrict__ h, const int* __restrict__ src,
    const int* __restrict__ dst)
{
    long long gid = (long long)blockIdx.x * blockDim.x + threadIdx.x;
    int e = (int)(gid >> 5);
    int lane = (int)(gid & 31);
    if (e >= NE) return;
    int s = 0, d = 0;
    if (lane == 0) { s = src[e]; d = dst[e]; }
    s = __shfl_sync(0xFFFFFFFFu, s, 0);
    d = __shfl_sync(0xFFFFFFFFu, d, 0);
    float4 v = ((const float4*)h)[(long long)s * 32 + lane];
    float* out = g_agg + (long long)d * HD + lane * 4;
    asm volatile("red.global.add.v4.f32 [%0], {%1, %2, %3, %4};"
                 :: "l"(out), "f"(v.x), "f"(v.y), "f"(v.z), "f"(v.w)
                 : "memory");
}

// ---------------- GEMM1: x = ((1+eps)*h + agg) @ W + b, fused BN stats ----
// BM=64, BN=128, K=128 in two 64-chunks. 256 threads, 4x8 register tile.
__global__ __launch_bounds__(256) void gemm_stats_kernel(
    const float* __restrict__ hin, const float* __restrict__ agg,
    const float* __restrict__ W, const float* __restrict__ bias,
    const float* __restrict__ eps_ptr, float* __restrict__ out)
{
    __shared__ float a_s[64 * 64];    // [k][row]
    __shared__ float w_s[64 * 128];   // [k][col]
    int tid = threadIdx.x;
    int tr = tid >> 4;      // 0..15 -> rows 4*tr..
    int tc = tid & 15;      // 0..15 -> cols 8*tc..
    int row0 = blockIdx.x * 64;
    float eps1 = 1.0f + eps_ptr[0];

    float acc[4][8];
#pragma unroll
    for (int i = 0; i < 4; i++)
#pragma unroll
        for (int j = 0; j < 8; j++) acc[i][j] = 0.f;

    for (int kc = 0; kc < 2; kc++) {
        int kbase = kc * 64;
        // stage A (transposed): 64 rows x 64 k
        {
            int r = tid & 63;
            int q0 = tid >> 6;  // 0..3
            int grow = row0 + r;
#pragma unroll
            for (int p = 0; p < 4; p++) {
                int k = (q0 + p * 4) * 4;  // covers 64 k in float4s
                float4 v = make_float4(0.f, 0.f, 0.f, 0.f);
                if (grow < NN) {
                    float4 hv = *(const float4*)&hin[(long long)grow * HD + kbase + k];
                    float4 av = *(const float4*)&agg[(long long)grow * HD + kbase + k];
                    v.x = eps1 * hv.x + av.x;
                    v.y = eps1 * hv.y + av.y;
                    v.z = eps1 * hv.z + av.z;
                    v.w = eps1 * hv.w + av.w;
                }
                a_s[(k + 0) * 64 + r] = v.x;
                a_s[(k + 1) * 64 + r] = v.y;
                a_s[(k + 2) * 64 + r] = v.z;
                a_s[(k + 3) * 64 + r] = v.w;
            }
        }
        // stage W: 64 k x 128 cols
        {
#pragma unroll
            for (int p = 0; p < 8; p++) {
                int idx = tid + p * 256;   // 0..2047 float4s
                int k = idx >> 5;
                int q = idx & 31;
                *(float4*)&w_s[k * 128 + q * 4] =
                    *(const float4*)&W[(long long)(kbase + k) * HD + q * 4];
            }
        }
        __syncthreads();
#pragma unroll 8
        for (int k = 0; k < 64; k++) {
            float4 av = *(const float4*)(a_s + k * 64 + 4 * tr);
            float4 w0 = *(const float4*)(w_s + k * 128 + 8 * tc);
            float4 w1 = *(const float4*)(w_s + k * 128 + 8 * tc + 4);
            float ar[4] = {av.x, av.y, av.z, av.w};
            float wr[8] = {w0.x, w0.y, w0.z, w0.w, w1.x, w1.y, w1.z, w1.w};
#pragma unroll
            for (int i = 0; i < 4; i++)
#pragma unroll
                for (int j = 0; j < 8; j++)
                    acc[i][j] = fmaf(ar[i], wr[j], acc[i][j]);
        }
        __syncthreads();
    }

    // epilogue: bias, store, BN stats
    float* s_sum = a_s;         // reuse smem (256 floats)
    float* s_sq = a_s + HD;
    if (tid < 64) ((float4*)s_sum)[tid] = make_float4(0.f, 0.f, 0.f, 0.f);
    __syncthreads();

    float colsum[8], colsq[8];
#pragma unroll
    for (int j = 0; j < 8; j++) { colsum[j] = 0.f; colsq[j] = 0.f; }
#pragma unroll
    for (int i = 0; i < 4; i++) {
        int grow = row0 + 4 * tr + i;
        if (grow < NN) {
            float vals[8];
#pragma unroll
            for (int j = 0; j < 8; j++) {
                float v = acc[i][j] + bias[8 * tc + j];
                vals[j] = v;
                colsum[j] += v;
                colsq[j] += v * v;
            }
            *(float4*)&out[(long long)grow * HD + 8 * tc] =
                make_float4(vals[0], vals[1], vals[2], vals[3]);
            *(float4*)&out[(long long)grow * HD + 8 * tc + 4] =
                make_float4(vals[4], vals[5], vals[6], vals[7]);
        }
    }
#pragma unroll
    for (int j = 0; j < 8; j++) {
        atomicAdd(&s_sum[8 * tc + j], colsum[j]);
        atomicAdd(&s_sq[8 * tc + j], colsq[j]);
    }
    __syncthreads();
    if (tid < HD) {
        atomicAdd(&g_stats[tid], s_sum[tid]);
        atomicAdd(&g_stats[HD + tid], s_sq[tid]);
    }
}

// ---------------- finalize BN stats -> per-channel scale/shift ------------
__global__ void finalize_stats_kernel(const float* __restrict__ gamma,
                                      const float* __restrict__ beta)
{
    int c = threadIdx.x;
    const float inv = 1.0f / (float)NN;
    float mean = g_stats[c] * inv;
    float var = g_stats[HD + c] * inv - mean * mean;
    float sc = gamma[c] * rsqrtf(var + BN_EPS);
    g_scale[c] = sc;
    g_shift[c] = beta[c] - mean * sc;
}

// ---------------- GEMM2: out = relu?(relu(BN(x)) @ W + b) ----------------
__global__ __launch_bounds__(256) void gemm_bn_kernel(
    const float* __restrict__ xin, const float* __restrict__ W,
    const float* __restrict__ bias, float* __restrict__ out, int relu_out)
{
    __shared__ float a_s[64 * 64];
    __shared__ float w_s[64 * 128];
    int tid = threadIdx.x;
    int tr = tid >> 4;
    int tc = tid & 15;
    int row0 = blockIdx.x * 64;

    float acc[4][8];
#pragma unroll
    for (int i = 0; i < 4; i++)
#pragma unroll
        for (int j = 0; j < 8; j++) acc[i][j] = 0.f;

    for (int kc = 0; kc < 2; kc++) {
        int kbase = kc * 64;
        {
            int r = tid & 63;
            int q0 = tid >> 6;
            int grow = row0 + r;
#pragma unroll
            for (int p = 0; p < 4; p++) {
                int k = (q0 + p * 4) * 4;
                float4 v = make_float4(0.f, 0.f, 0.f, 0.f);
                if (grow < NN) {
                    float4 xv = *(const float4*)&xin[(long long)grow * HD + kbase + k];
                    v.x = fmaxf(xv.x * g_scale[kbase + k + 0] + g_shift[kbase + k + 0], 0.f);
                    v.y = fmaxf(xv.y * g_scale[kbase + k + 1] + g_shift[kbase + k + 1], 0.f);
                    v.z = fmaxf(xv.z * g_scale[kbase + k + 2] + g_shift[kbase + k + 2], 0.f);
                    v.w = fmaxf(xv.w * g_scale[kbase + k + 3] + g_shift[kbase + k + 3], 0.f);
                }
                a_s[(k + 0) * 64 + r] = v.x;
                a_s[(k + 1) * 64 + r] = v.y;
                a_s[(k + 2) * 64 + r] = v.z;
                a_s[(k + 3) * 64 + r] = v.w;
            }
        }
        {
#pragma unroll
            for (int p = 0; p < 8; p++) {
                int idx = tid + p * 256;
                int k = idx >> 5;
                int q = idx & 31;
                *(float4*)&w_s[k * 128 + q * 4] =
                    *(const float4*)&W[(long long)(kbase + k) * HD + q * 4];
            }
        }
        __syncthreads();
#pragma unroll 8
        for (int k = 0; k < 64; k++) {
            float4 av = *(const float4*)(a_s + k * 64 + 4 * tr);
            float4 w0 = *(const float4*)(w_s + k * 128 + 8 * tc);
            float4 w1 = *(const float4*)(w_s + k * 128 + 8 * tc + 4);
            float ar[4] = {av.x, av.y, av.z, av.w};
            float wr[8] = {w0.x, w0.y, w0.z, w0.w, w1.x, w1.y, w1.z, w1.w};
#pragma unroll
            for (int i = 0; i < 4; i++)
#pragma unroll
                for (int j = 0; j < 8; j++)
                    acc[i][j] = fmaf(ar[i], wr[j], acc[i][j]);
        }
        __syncthreads();
    }

#pragma unroll
    for (int i = 0; i < 4; i++) {
        int grow = row0 + 4 * tr + i;
        if (grow < NN) {
            float vals[8];
#pragma unroll
            for (int j = 0; j < 8; j++) {
                float v = acc[i][j] + bias[8 * tc + j];
                if (relu_out) v = fmaxf(v, 0.f);
                vals[j] = v;
            }
            *(float4*)&out[(long long)grow * HD + 8 * tc] =
                make_float4(vals[0], vals[1], vals[2], vals[3]);
            *(float4*)&out[(long long)grow * HD + 8 * tc + 4] =
                make_float4(vals[4], vals[5], vals[6], vals[7]);
        }
    }
}

// ---------------- per-graph readout (graph_ids sorted) --------------------
__global__ __launch_bounds__(256) void readout_kernel(const int* __restrict__ gids)
{
    int c = threadIdx.x;                 // 0..255 output column
    const float* h = (c < HD) ? g_enc0 : g_enc1;
    int cc = c & (HD - 1);
    int n0 = blockIdx.x * 128;
    int n1 = n0 + 128;
    if (n1 > NN) n1 = NN;
    int cur = gids[n0];
    float acc = 0.f;
    for (int n = n0; n < n1; n++) {
        int g = gids[n];
        if (g != cur) {
            atomicAdd(&g_hg[cur * 2 * HD + c], acc);
            acc = 0.f;
            cur = g;
        }
        acc += h[(long long)n * HD + cc];
    }
    atomicAdd(&g_hg[cur * 2 * HD + c], acc);
}

// ---------------- output MLP ----------------
__global__ void mlp1_kernel(const float* __restrict__ W, const float* __restrict__ b)
{
    __shared__ float row[2 * HD];
    int g = blockIdx.x, c = threadIdx.x;
    row[c] = g_hg[g * 2 * HD + c];
    row[c + HD] = g_hg[g * 2 * HD + c + HD];
    __syncthreads();
    float acc = b[c];
#pragma unroll 4
    for (int k = 0; k < 2 * HD; k++) acc = fmaf(row[k], W[k * HD + c], acc);
    g_m1[g * HD + c] = fmaxf(acc, 0.f);
}

__global__ void mlp2_kernel(const float* __restrict__ W, const float* __restrict__ b)
{
    __shared__ float row[HD];
    int g = blockIdx.x, c = threadIdx.x;
    row[c] = g_m1[g * HD + c];
    __syncthreads();
    float acc = b[c];
#pragma unroll 4
    for (int k = 0; k < HD; k++) acc = fmaf(row[k], W[k * HD + c], acc);
    g_m2[g * HD + c] = fmaxf(acc, 0.f);
}

__global__ void mlp3_kernel(const float* __restrict__ W, const float* __restrict__ b,
                            float* __restrict__ out)
{
    int g = threadIdx.x;
    if (g < NG) {
        float acc = b[0];
#pragma unroll 4
        for (int k = 0; k < HD; k++) acc = fmaf(g_m2[g * HD + k], W[k], acc);
        out[g] = acc;
    }
}

// ---------------- launch ----------------
extern "C" void kernel_launch(void* const* d_in, const int* in_sizes, int n_in,
                              void* d_out, int out_size)
{
    const float* feats = (const float*)d_in[0];
    const int* src = (const int*)d_in[1];
    const int* dst = (const int*)d_in[2];
    const int* gids = (const int*)d_in[3];
    // d_in[4] = n_graphs (always 256)
    const float* eps = (const float*)d_in[5];
    const float* Wa = (const float*)d_in[6];
    const float* ba = (const float*)d_in[7];
    const float* bng = (const float*)d_in[8];
    const float* bnb = (const float*)d_in[9];
    const float* Wb = (const float*)d_in[10];
    const float* bb = (const float*)d_in[11];
    const float* oW1 = (const float*)d_in[12];
    const float* ob1 = (const float*)d_in[13];
    const float* oW2 = (const float*)d_in[14];
    const float* ob2 = (const float*)d_in[15];
    const float* oW3 = (const float*)d_in[16];
    const float* ob3 = (const float*)d_in[17];
    float* out = (float*)d_out;

    float *aggp, *xp, *bufp, *e0p, *e1p;
    cudaGetSymbolAddress((void**)&aggp, g_agg);
    cudaGetSymbolAddress((void**)&xp, g_x);
    cudaGetSymbolAddress((void**)&bufp, g_buf);
    cudaGetSymbolAddress((void**)&e0p, g_enc0);
    cudaGetSymbolAddress((void**)&e1p, g_enc1);

    const int gemm_blocks = (NN + 63) / 64;          // 782
    const int agg_blocks = (NE * 32 + 255) / 256;    // 100000
    const int zero_blocks = (NN * HD / 4 + 255) / 256;

    for (int e = 0; e < 2; e++) {
        const int* se = src + e * NE;
        const int* de = dst + e * NE;
        float* enc = e ? e1p : e0p;
        const float* hin = feats;
        for (int l = 0; l < 2; l++) {
            int wl = e * 2 + l;
            zero_agg_stats_kernel<<<zero_blocks, 256>>>();
            agg_kernel<<<agg_blocks, 256>>>(hin, se, de);
            gemm_stats_kernel<<<gemm_blocks, 256>>>(
                hin, aggp, Wa + (long long)wl * HD * HD, ba + wl * HD, eps + wl, xp);
            finalize_stats_kernel<<<1, HD>>>(bng + wl * HD, bnb + wl * HD);
            float* o = (l == 0) ? bufp : enc;
            gemm_bn_kernel<<<gemm_blocks, 256>>>(
                xp, Wb + (long long)wl * HD * HD, bb + wl * HD, o, (l == 0) ? 1 : 0);
            hin = bufp;
        }
    }

    zero_hg_kernel<<<(NG * 2 * HD / 4 + 255) / 256, 256>>>();
    readout_kernel<<<(NN + 127) / 128, 256>>>(gids);
    mlp1_kernel<<<NG, HD>>>(oW1, ob1);
    mlp2_kernel<<<NG, HD>>>(oW2, ob2);
    mlp3_kernel<<<1, NG>>>(oW3, ob3, out);
}

// round 4
// speedup vs baseline: 1.8828x; 1.3529x over previous
#include <cuda_runtime.h>
#include <math.h>

#define NN 50000
#define NE 800000
#define NG 256
#define HD 128
#define BN_EPS 1e-5f

// ---------------- device scratch (no allocation allowed) ----------------
__device__ float g_agg[NN * HD];     // holds x-input = (1+eps)h + sum_nbr h
__device__ float g_x[NN * HD];
__device__ float g_buf[NN * HD];
__device__ float g_enc0[NN * HD];
__device__ float g_enc1[NN * HD];
__device__ float g_stats[2 * HD];
__device__ float g_scale[HD];
__device__ float g_shift[HD];
__device__ float g_hg[NG * 2 * HD];
__device__ float g_m1[NG * HD];
__device__ float g_m2[NG * HD];
// CSR scratch
__device__ int g_deg[NN];
__device__ int g_rowstart[NN + 1];
__device__ int g_cursor[NN];
__device__ int g_eidx0[NE];
__device__ int g_eidx1[NE];

// ---------------- small utility kernels ----------------
__global__ void zero_deg_kernel() {
    int i = blockIdx.x * blockDim.x + threadIdx.x;
    if (i < NN) g_deg[i] = 0;
}

__global__ void zero_stats_kernel() {
    int i = threadIdx.x;
    if (i < (2 * HD) / 4) ((float4*)g_stats)[i] = make_float4(0.f, 0.f, 0.f, 0.f);
}

__global__ void zero_hg_kernel() {
    int i = blockIdx.x * blockDim.x + threadIdx.x;
    if (i < NG * 2 * HD / 4) ((float4*)g_hg)[i] = make_float4(0.f, 0.f, 0.f, 0.f);
}

// ---------------- CSR build ----------------
__global__ __launch_bounds__(256) void deg_kernel(const int* __restrict__ dst) {
    int i = blockIdx.x * blockDim.x + threadIdx.x;
    if (i < NE) atomicAdd(&g_deg[dst[i]], 1);
}

__global__ __launch_bounds__(1024) void scan_kernel() {
    __shared__ int ssum[1024];
    int t = threadIdx.x;
    const int CH = (NN + 1023) / 1024;   // 49
    int start = t * CH;
    int end = start + CH; if (end > NN) end = NN;
    if (start > NN) start = NN;
    int s = 0;
    for (int i = start; i < end; i++) s += g_deg[i];
    ssum[t] = s;
    __syncthreads();
    for (int off = 1; off < 1024; off <<= 1) {
        int v = (t >= off) ? ssum[t - off] : 0;
        __syncthreads();
        ssum[t] += v;
        __syncthreads();
    }
    int base = (t == 0) ? 0 : ssum[t - 1];
    for (int i = start; i < end; i++) {
        int d = g_deg[i];
        g_rowstart[i] = base;
        g_cursor[i] = base;
        base += d;
    }
    if (t == 1023) g_rowstart[NN] = base;
}

__global__ __launch_bounds__(256) void scatter_kernel(
    const int* __restrict__ src, const int* __restrict__ dst,
    int* __restrict__ eidx)
{
    int i = blockIdx.x * blockDim.x + threadIdx.x;
    if (i < NE) {
        int p = atomicAdd(&g_cursor[dst[i]], 1);
        eidx[p] = src[i];
    }
}

// -------- CSR aggregation: xout[n] = (1+eps)*h[n] + sum_{j in N(n)} h[j] ----
// one warp per node; lane owns one float4 column slice; no atomics
__global__ __launch_bounds__(256) void agg_csr_kernel(
    const float* __restrict__ h, const int* __restrict__ eidx,
    const float* __restrict__ eps_ptr, float* __restrict__ xout)
{
    int warp = (blockIdx.x * 256 + threadIdx.x) >> 5;
    int lane = threadIdx.x & 31;
    if (warp >= NN) return;
    int ro = g_rowstart[warp];
    int re = g_rowstart[warp + 1];
    float eps1 = 1.0f + eps_ptr[0];
    float4 hv = ((const float4*)h)[(long long)warp * 32 + lane];
    float4 acc = make_float4(eps1 * hv.x, eps1 * hv.y, eps1 * hv.z, eps1 * hv.w);
    int j = ro;
    for (; j + 4 <= re; j += 4) {
        int s0 = eidx[j], s1 = eidx[j + 1], s2 = eidx[j + 2], s3 = eidx[j + 3];
        float4 v0 = ((const float4*)h)[(long long)s0 * 32 + lane];
        float4 v1 = ((const float4*)h)[(long long)s1 * 32 + lane];
        float4 v2 = ((const float4*)h)[(long long)s2 * 32 + lane];
        float4 v3 = ((const float4*)h)[(long long)s3 * 32 + lane];
        acc.x += v0.x + v1.x + v2.x + v3.x;
        acc.y += v0.y + v1.y + v2.y + v3.y;
        acc.z += v0.z + v1.z + v2.z + v3.z;
        acc.w += v0.w + v1.w + v2.w + v3.w;
    }
    for (; j < re; j++) {
        int s = eidx[j];
        float4 v = ((const float4*)h)[(long long)s * 32 + lane];
        acc.x += v.x; acc.y += v.y; acc.z += v.z; acc.w += v.w;
    }
    ((float4*)xout)[(long long)warp * 32 + lane] = acc;
}

// ---------------- GEMM1: x = xin @ W + b, fused BN stats ----
// BM=128, BN=128, K=128 (2 chunks of 64). 256 threads, 8x8 split-col tile.
__global__ __launch_bounds__(256) void gemm_stats_kernel(
    const float* __restrict__ xin,
    const float* __restrict__ W, const float* __restrict__ bias,
    float* __restrict__ out)
{
    __shared__ float a_s[64 * 128];    // [k][row]
    __shared__ float w_s[64 * 128];    // [k][col]
    int tid = threadIdx.x;
    int tr = tid >> 4;      // 0..15: rows {4tr..4tr+3, 64+4tr..}
    int tc = tid & 15;      // 0..15: cols {4tc..4tc+3, 64+4tc..}
    int row0 = blockIdx.x * 128;

    float acc[8][8];
#pragma unroll
    for (int i = 0; i < 8; i++)
#pragma unroll
        for (int j = 0; j < 8; j++) acc[i][j] = 0.f;

    for (int kc = 0; kc < 2; kc++) {
        int kbase = kc * 64;
        // stage A transposed: 128 rows x 64 k
        {
            int r = tid & 127;
            int half = tid >> 7;
            int grow = row0 + r;
#pragma unroll
            for (int p = 0; p < 8; p++) {
                int kf4 = half + 2 * p;           // 0..15
                int k = 4 * kf4;
                float4 v = make_float4(0.f, 0.f, 0.f, 0.f);
                if (grow < NN)
                    v = *(const float4*)&xin[(long long)grow * HD + kbase + k];
                a_s[(k + 0) * 128 + r] = v.x;
                a_s[(k + 1) * 128 + r] = v.y;
                a_s[(k + 2) * 128 + r] = v.z;
                a_s[(k + 3) * 128 + r] = v.w;
            }
        }
        // stage W: 64 k x 128 cols
        {
#pragma unroll
            for (int p = 0; p < 8; p++) {
                int idx = tid + p * 256;
                int k = idx >> 5;
                int q = idx & 31;
                *(float4*)&w_s[k * 128 + q * 4] =
                    *(const float4*)&W[(long long)(kbase + k) * HD + q * 4];
            }
        }
        __syncthreads();
#pragma unroll 4
        for (int k = 0; k < 64; k++) {
            float4 a0 = *(const float4*)(a_s + k * 128 + 4 * tr);
            float4 a1 = *(const float4*)(a_s + k * 128 + 64 + 4 * tr);
            float4 w0 = *(const float4*)(w_s + k * 128 + 4 * tc);
            float4 w1 = *(const float4*)(w_s + k * 128 + 64 + 4 * tc);
            float ar[8] = {a0.x, a0.y, a0.z, a0.w, a1.x, a1.y, a1.z, a1.w};
            float wr[8] = {w0.x, w0.y, w0.z, w0.w, w1.x, w1.y, w1.z, w1.w};
#pragma unroll
            for (int i = 0; i < 8; i++)
#pragma unroll
                for (int j = 0; j < 8; j++)
                    acc[i][j] = fmaf(ar[i], wr[j], acc[i][j]);
        }
        __syncthreads();
    }

    // epilogue: bias, store, BN stats
    float* s_sum = a_s;
    float* s_sq = a_s + HD;
    if (tid < 64) ((float4*)s_sum)[tid] = make_float4(0.f, 0.f, 0.f, 0.f);
    __syncthreads();

    float bv[8];
#pragma unroll
    for (int j = 0; j < 8; j++)
        bv[j] = bias[(j < 4) ? (4 * tc + j) : (64 + 4 * tc + j - 4)];

    float colsum[8], colsq[8];
#pragma unroll
    for (int j = 0; j < 8; j++) { colsum[j] = 0.f; colsq[j] = 0.f; }
#pragma unroll
    for (int i = 0; i < 8; i++) {
        int grow = row0 + ((i < 4) ? (4 * tr + i) : (64 + 4 * tr + i - 4));
        if (grow < NN) {
            float vals[8];
#pragma unroll
            for (int j = 0; j < 8; j++) {
                float v = acc[i][j] + bv[j];
                vals[j] = v;
                colsum[j] += v;
                colsq[j] += v * v;
            }
            *(float4*)&out[(long long)grow * HD + 4 * tc] =
                make_float4(vals[0], vals[1], vals[2], vals[3]);
            *(float4*)&out[(long long)grow * HD + 64 + 4 * tc] =
                make_float4(vals[4], vals[5], vals[6], vals[7]);
        }
    }
#pragma unroll
    for (int j = 0; j < 8; j++) {
        int c = (j < 4) ? (4 * tc + j) : (64 + 4 * tc + j - 4);
        atomicAdd(&s_sum[c], colsum[j]);
        atomicAdd(&s_sq[c], colsq[j]);
    }
    __syncthreads();
    if (tid < HD) {
        atomicAdd(&g_stats[tid], s_sum[tid]);
        atomicAdd(&g_stats[HD + tid], s_sq[tid]);
    }
}

// ---------------- finalize BN stats -> per-channel scale/shift ------------
__global__ void finalize_stats_kernel(const float* __restrict__ gamma,
                                      const float* __restrict__ beta)
{
    int c = threadIdx.x;
    const float inv = 1.0f / (float)NN;
    float mean = g_stats[c] * inv;
    float var = g_stats[HD + c] * inv - mean * mean;
    float sc = gamma[c] * rsqrtf(var + BN_EPS);
    g_scale[c] = sc;
    g_shift[c] = beta[c] - mean * sc;
}

// ---------------- GEMM2: out = relu?(relu(BN(x)) @ W + b) ----------------
__global__ __launch_bounds__(256) void gemm_bn_kernel(
    const float* __restrict__ xin, const float* __restrict__ W,
    const float* __restrict__ bias, float* __restrict__ out, int relu_out)
{
    __shared__ float a_s[64 * 128];
    __shared__ float w_s[64 * 128];
    int tid = threadIdx.x;
    int tr = tid >> 4;
    int tc = tid & 15;
    int row0 = blockIdx.x * 128;

    float acc[8][8];
#pragma unroll
    for (int i = 0; i < 8; i++)
#pragma unroll
        for (int j = 0; j < 8; j++) acc[i][j] = 0.f;

    for (int kc = 0; kc < 2; kc++) {
        int kbase = kc * 64;
        {
            int r = tid & 127;
            int half = tid >> 7;
            int grow = row0 + r;
#pragma unroll
            for (int p = 0; p < 8; p++) {
                int kf4 = half + 2 * p;
                int k = 4 * kf4;
                float4 v = make_float4(0.f, 0.f, 0.f, 0.f);
                if (grow < NN) {
                    float4 xv = *(const float4*)&xin[(long long)grow * HD + kbase + k];
                    v.x = fmaxf(xv.x * g_scale[kbase + k + 0] + g_shift[kbase + k + 0], 0.f);
                    v.y = fmaxf(xv.y * g_scale[kbase + k + 1] + g_shift[kbase + k + 1], 0.f);
                    v.z = fmaxf(xv.z * g_scale[kbase + k + 2] + g_shift[kbase + k + 2], 0.f);
                    v.w = fmaxf(xv.w * g_scale[kbase + k + 3] + g_shift[kbase + k + 3], 0.f);
                }
                a_s[(k + 0) * 128 + r] = v.x;
                a_s[(k + 1) * 128 + r] = v.y;
                a_s[(k + 2) * 128 + r] = v.z;
                a_s[(k + 3) * 128 + r] = v.w;
            }
        }
        {
#pragma unroll
            for (int p = 0; p < 8; p++) {
                int idx = tid + p * 256;
                int k = idx >> 5;
                int q = idx & 31;
                *(float4*)&w_s[k * 128 + q * 4] =
                    *(const float4*)&W[(long long)(kbase + k) * HD + q * 4];
            }
        }
        __syncthreads();
#pragma unroll 4
        for (int k = 0; k < 64; k++) {
            float4 a0 = *(const float4*)(a_s + k * 128 + 4 * tr);
            float4 a1 = *(const float4*)(a_s + k * 128 + 64 + 4 * tr);
            float4 w0 = *(const float4*)(w_s + k * 128 + 4 * tc);
            float4 w1 = *(const float4*)(w_s + k * 128 + 64 + 4 * tc);
            float ar[8] = {a0.x, a0.y, a0.z, a0.w, a1.x, a1.y, a1.z, a1.w};
            float wr[8] = {w0.x, w0.y, w0.z, w0.w, w1.x, w1.y, w1.z, w1.w};
#pragma unroll
            for (int i = 0; i < 8; i++)
#pragma unroll
                for (int j = 0; j < 8; j++)
                    acc[i][j] = fmaf(ar[i], wr[j], acc[i][j]);
        }
        __syncthreads();
    }

    float bv[8];
#pragma unroll
    for (int j = 0; j < 8; j++)
        bv[j] = bias[(j < 4) ? (4 * tc + j) : (64 + 4 * tc + j - 4)];

#pragma unroll
    for (int i = 0; i < 8; i++) {
        int grow = row0 + ((i < 4) ? (4 * tr + i) : (64 + 4 * tr + i - 4));
        if (grow < NN) {
            float vals[8];
#pragma unroll
            for (int j = 0; j < 8; j++) {
                float v = acc[i][j] + bv[j];
                if (relu_out) v = fmaxf(v, 0.f);
                vals[j] = v;
            }
            *(float4*)&out[(long long)grow * HD + 4 * tc] =
                make_float4(vals[0], vals[1], vals[2], vals[3]);
            *(float4*)&out[(long long)grow * HD + 64 + 4 * tc] =
                make_float4(vals[4], vals[5], vals[6], vals[7]);
        }
    }
}

// ---------------- per-graph readout (graph_ids sorted) --------------------
__global__ __launch_bounds__(256) void readout_kernel(const int* __restrict__ gids)
{
    int c = threadIdx.x;
    const float* h = (c < HD) ? g_enc0 : g_enc1;
    int cc = c & (HD - 1);
    int n0 = blockIdx.x * 128;
    int n1 = n0 + 128;
    if (n1 > NN) n1 = NN;
    int cur = gids[n0];
    float acc = 0.f;
    for (int n = n0; n < n1; n++) {
        int g = gids[n];
        if (g != cur) {
            atomicAdd(&g_hg[cur * 2 * HD + c], acc);
            acc = 0.f;
            cur = g;
        }
        acc += h[(long long)n * HD + cc];
    }
    atomicAdd(&g_hg[cur * 2 * HD + c], acc);
}

// ---------------- output MLP ----------------
__global__ void mlp1_kernel(const float* __restrict__ W, const float* __restrict__ b)
{
    __shared__ float row[2 * HD];
    int g = blockIdx.x, c = threadIdx.x;
    row[c] = g_hg[g * 2 * HD + c];
    row[c + HD] = g_hg[g * 2 * HD + c + HD];
    __syncthreads();
    float acc = b[c];
#pragma unroll 4
    for (int k = 0; k < 2 * HD; k++) acc = fmaf(row[k], W[k * HD + c], acc);
    g_m1[g * HD + c] = fmaxf(acc, 0.f);
}

__global__ void mlp2_kernel(const float* __restrict__ W, const float* __restrict__ b)
{
    __shared__ float row[HD];
    int g = blockIdx.x, c = threadIdx.x;
    row[c] = g_m1[g * HD + c];
    __syncthreads();
    float acc = b[c];
#pragma unroll 4
    for (int k = 0; k < HD; k++) acc = fmaf(row[k], W[k * HD + c], acc);
    g_m2[g * HD + c] = fmaxf(acc, 0.f);
}

__global__ void mlp3_kernel(const float* __restrict__ W, const float* __restrict__ b,
                            float* __restrict__ out)
{
    int g = threadIdx.x;
    if (g < NG) {
        float acc = b[0];
#pragma unroll 4
        for (int k = 0; k < HD; k++) acc = fmaf(g_m2[g * HD + k], W[k], acc);
        out[g] = acc;
    }
}

// ---------------- launch ----------------
extern "C" void kernel_launch(void* const* d_in, const int* in_sizes, int n_in,
                              void* d_out, int out_size)
{
    const float* feats = (const float*)d_in[0];
    const int* src = (const int*)d_in[1];
    const int* dst = (const int*)d_in[2];
    const int* gids = (const int*)d_in[3];
    const float* eps = (const float*)d_in[5];
    const float* Wa = (const float*)d_in[6];
    const float* ba = (const float*)d_in[7];
    const float* bng = (const float*)d_in[8];
    const float* bnb = (const float*)d_in[9];
    const float* Wb = (const float*)d_in[10];
    const float* bb = (const float*)d_in[11];
    const float* oW1 = (const float*)d_in[12];
    const float* ob1 = (const float*)d_in[13];
    const float* oW2 = (const float*)d_in[14];
    const float* ob2 = (const float*)d_in[15];
    const float* oW3 = (const float*)d_in[16];
    const float* ob3 = (const float*)d_in[17];
    float* out = (float*)d_out;

    float *aggp, *xp, *bufp, *e0p, *e1p;
    cudaGetSymbolAddress((void**)&aggp, g_agg);
    cudaGetSymbolAddress((void**)&xp, g_x);
    cudaGetSymbolAddress((void**)&bufp, g_buf);
    cudaGetSymbolAddress((void**)&e0p, g_enc0);
    cudaGetSymbolAddress((void**)&e1p, g_enc1);
    int *ei0p, *ei1p;
    cudaGetSymbolAddress((void**)&ei0p, g_eidx0);
    cudaGetSymbolAddress((void**)&ei1p, g_eidx1);

    const int gemm_blocks = (NN + 127) / 128;        // 391
    const int edge_blocks = (NE + 255) / 256;        // 3125
    const int node_blocks = (NN + 255) / 256;        // 196
    const int agg_blocks = (NN * 32 + 255) / 256;    // 6250

    // Build CSR for each encoder's edge list (shared by both layers)
    for (int e = 0; e < 2; e++) {
        int* eidx = e ? ei1p : ei0p;
        zero_deg_kernel<<<node_blocks, 256>>>();
        deg_kernel<<<edge_blocks, 256>>>(dst + (long long)e * NE);
        scan_kernel<<<1, 1024>>>();
        scatter_kernel<<<edge_blocks, 256>>>(src + (long long)e * NE,
                                             dst + (long long)e * NE, eidx);

        float* enc = e ? e1p : e0p;
        const float* hin = feats;
        for (int l = 0; l < 2; l++) {
            int wl = e * 2 + l;
            zero_stats_kernel<<<1, 64>>>();
            agg_csr_kernel<<<agg_blocks, 256>>>(hin, eidx, eps + wl, aggp);
            gemm_stats_kernel<<<gemm_blocks, 256>>>(
                aggp, Wa + (long long)wl * HD * HD, ba + wl * HD, xp);
            finalize_stats_kernel<<<1, HD>>>(bng + wl * HD, bnb + wl * HD);
            float* o = (l == 0) ? bufp : enc;
            gemm_bn_kernel<<<gemm_blocks, 256>>>(
                xp, Wb + (long long)wl * HD * HD, bb + wl * HD, o, (l == 0) ? 1 : 0);
            hin = bufp;
        }
    }

    zero_hg_kernel<<<(NG * 2 * HD / 4 + 255) / 256, 256>>>();
    readout_kernel<<<(NN + 127) / 128, 256>>>(gids);
    mlp1_kernel<<<NG, HD>>>(oW1, ob1);
    mlp2_kernel<<<NG, HD>>>(oW2, ob2);
    mlp3_kernel<<<1, NG>>>(oW3, ob3, out);
}

// round 5
// speedup vs baseline: 2.0456x; 1.0865x over previous
#include <cuda_runtime.h>
#include <math.h>

#define NN 50000
#define NE 800000
#define NG 256
#define HD 128
#define BN_EPS 1e-5f

// ---------------- device scratch (no allocation allowed) ----------------
__device__ float g_agg[NN * HD];     // x-input = (1+eps)h + sum_nbr h
__device__ float g_x[NN * HD];
__device__ float g_buf[NN * HD];
__device__ float g_enc0[NN * HD];
__device__ float g_enc1[NN * HD];
__device__ float g_stats[2 * HD];
__device__ float g_scale[HD];
__device__ float g_shift[HD];
__device__ float g_hg[NG * 2 * HD];
__device__ float g_m1[NG * HD];
__device__ float g_m2[NG * HD];
// CSR scratch
__device__ int g_deg[NN];
__device__ int g_rowstart[NN + 1];
__device__ int g_cursor[NN];
__device__ int g_eidx0[NE];
__device__ int g_eidx1[NE];

// ---------------- CSR build ----------------
__global__ __launch_bounds__(256) void deg_kernel(const int* __restrict__ dst) {
    int i = blockIdx.x * blockDim.x + threadIdx.x;
    if (i < NE) atomicAdd(&g_deg[dst[i]], 1);
}

__global__ __launch_bounds__(1024) void scan_kernel() {
    __shared__ int ssum[1024];
    int t = threadIdx.x;
    const int CH = (NN + 1023) / 1024;   // 49
    int start = t * CH;
    int end = start + CH; if (end > NN) end = NN;
    if (start > NN) start = NN;
    int s = 0;
    for (int i = start; i < end; i++) s += g_deg[i];
    ssum[t] = s;
    __syncthreads();
    for (int off = 1; off < 1024; off <<= 1) {
        int v = (t >= off) ? ssum[t - off] : 0;
        __syncthreads();
        ssum[t] += v;
        __syncthreads();
    }
    int base = (t == 0) ? 0 : ssum[t - 1];
    for (int i = start; i < end; i++) {
        int d = g_deg[i];
        g_rowstart[i] = base;
        g_cursor[i] = base;
        base += d;
    }
    if (t == 1023) g_rowstart[NN] = base;
}

__global__ __launch_bounds__(256) void scatter_kernel(
    const int* __restrict__ src, const int* __restrict__ dst,
    int* __restrict__ eidx)
{
    int i = blockIdx.x * blockDim.x + threadIdx.x;
    if (i < NE) {
        int p = atomicAdd(&g_cursor[dst[i]], 1);
        eidx[p] = src[i];
    }
}

// -------- CSR aggregation: xout[n] = (1+eps)*h[n] + sum_{j in N(n)} h[j] ----
__global__ __launch_bounds__(256) void agg_csr_kernel(
    const float* __restrict__ h, const int* __restrict__ eidx,
    const float* __restrict__ eps_ptr, float* __restrict__ xout)
{
    int warp = (blockIdx.x * 256 + threadIdx.x) >> 5;
    int lane = threadIdx.x & 31;
    if (warp >= NN) return;
    int ro = g_rowstart[warp];
    int re = g_rowstart[warp + 1];
    float eps1 = 1.0f + eps_ptr[0];
    float4 hv = ((const float4*)h)[(long long)warp * 32 + lane];
    float4 acc = make_float4(eps1 * hv.x, eps1 * hv.y, eps1 * hv.z, eps1 * hv.w);
    int j = ro;
    for (; j + 4 <= re; j += 4) {
        int s0 = eidx[j], s1 = eidx[j + 1], s2 = eidx[j + 2], s3 = eidx[j + 3];
        float4 v0 = ((const float4*)h)[(long long)s0 * 32 + lane];
        float4 v1 = ((const float4*)h)[(long long)s1 * 32 + lane];
        float4 v2 = ((const float4*)h)[(long long)s2 * 32 + lane];
        float4 v3 = ((const float4*)h)[(long long)s3 * 32 + lane];
        acc.x += v0.x + v1.x + v2.x + v3.x;
        acc.y += v0.y + v1.y + v2.y + v3.y;
        acc.z += v0.z + v1.z + v2.z + v3.z;
        acc.w += v0.w + v1.w + v2.w + v3.w;
    }
    for (; j < re; j++) {
        int s = eidx[j];
        float4 v = ((const float4*)h)[(long long)s * 32 + lane];
        acc.x += v.x; acc.y += v.y; acc.z += v.z; acc.w += v.w;
    }
    ((float4*)xout)[(long long)warp * 32 + lane] = acc;
}

// ---- packed f32x2 helpers ----
__device__ __forceinline__ void ffma2(unsigned long long& acc,
                                      unsigned long long a, unsigned long long b) {
    asm("fma.rn.f32x2 %0, %1, %2, %0;" : "+l"(acc) : "l"(a), "l"(b));
}
__device__ __forceinline__ unsigned long long bcast2(float w) {
    unsigned long long r;
    unsigned int u = __float_as_uint(w);
    asm("mov.b64 %0, {%1, %2};" : "=l"(r) : "r"(u), "r"(u));
    return r;
}
__device__ __forceinline__ void unpack2(unsigned long long p, float& lo, float& hi) {
    unsigned int l, h;
    asm("mov.b64 {%0, %1}, %2;" : "=r"(l), "=r"(h) : "l"(p));
    lo = __uint_as_float(l);
    hi = __uint_as_float(h);
}

// ---------------- GEMM1: x = xin @ W + b, fused BN stats ----
// BM=128, BN=128, K=128 (2 chunks of 64). 256 threads, 8x8 tile via f32x2.
__global__ __launch_bounds__(256) void gemm_stats_kernel(
    const float* __restrict__ xin,
    const float* __restrict__ W, const float* __restrict__ bias,
    float* __restrict__ out)
{
    __shared__ float a_s[64 * 128];    // [k][row]
    __shared__ float w_s[64 * 128];    // [k][col]
    int tid = threadIdx.x;
    int tr = tid >> 4;
    int tc = tid & 15;
    int row0 = blockIdx.x * 128;

    unsigned long long accp[4][8];     // row-pairs x 8 cols
#pragma unroll
    for (int p = 0; p < 4; p++)
#pragma unroll
        for (int j = 0; j < 8; j++) accp[p][j] = 0ULL;

    for (int kc = 0; kc < 2; kc++) {
        int kbase = kc * 64;
        // stage A transposed: 128 rows x 64 k
        {
            int r = tid & 127;
            int half = tid >> 7;
            int grow = row0 + r;
#pragma unroll
            for (int p = 0; p < 8; p++) {
                int k = 4 * (half + 2 * p);
                float4 v = make_float4(0.f, 0.f, 0.f, 0.f);
                if (grow < NN)
                    v = *(const float4*)&xin[(long long)grow * HD + kbase + k];
                a_s[(k + 0) * 128 + r] = v.x;
                a_s[(k + 1) * 128 + r] = v.y;
                a_s[(k + 2) * 128 + r] = v.z;
                a_s[(k + 3) * 128 + r] = v.w;
            }
        }
        // stage W: 64 k x 128 cols
        {
#pragma unroll
            for (int p = 0; p < 8; p++) {
                int idx = tid + p * 256;
                int k = idx >> 5;
                int q = idx & 31;
                *(float4*)&w_s[k * 128 + q * 4] =
                    *(const float4*)&W[(long long)(kbase + k) * HD + q * 4];
            }
        }
        __syncthreads();
#pragma unroll 4
        for (int k = 0; k < 64; k++) {
            ulonglong2 av0 = *(const ulonglong2*)(a_s + k * 128 + 4 * tr);
            ulonglong2 av1 = *(const ulonglong2*)(a_s + k * 128 + 64 + 4 * tr);
            float4 w0 = *(const float4*)(w_s + k * 128 + 4 * tc);
            float4 w1 = *(const float4*)(w_s + k * 128 + 64 + 4 * tc);
            unsigned long long ap[4] = {av0.x, av0.y, av1.x, av1.y};
            unsigned long long wp[8] = {
                bcast2(w0.x), bcast2(w0.y), bcast2(w0.z), bcast2(w0.w),
                bcast2(w1.x), bcast2(w1.y), bcast2(w1.z), bcast2(w1.w)};
#pragma unroll
            for (int p = 0; p < 4; p++)
#pragma unroll
                for (int j = 0; j < 8; j++)
                    ffma2(accp[p][j], ap[p], wp[j]);
        }
        __syncthreads();
    }

    // unpack accumulators: i<4 -> row 4tr+i ; i>=4 -> row 64+4tr+(i-4)
    float accf[8][8];
#pragma unroll
    for (int p = 0; p < 4; p++)
#pragma unroll
        for (int j = 0; j < 8; j++)
            unpack2(accp[p][j], accf[2 * p][j], accf[2 * p + 1][j]);

    // epilogue: bias, store, BN stats
    float* s_sum = a_s;
    float* s_sq = a_s + HD;
    if (tid < 64) ((float4*)s_sum)[tid] = make_float4(0.f, 0.f, 0.f, 0.f);
    __syncthreads();

    float bv[8];
#pragma unroll
    for (int j = 0; j < 8; j++)
        bv[j] = bias[(j < 4) ? (4 * tc + j) : (64 + 4 * tc + j - 4)];

    float colsum[8], colsq[8];
#pragma unroll
    for (int j = 0; j < 8; j++) { colsum[j] = 0.f; colsq[j] = 0.f; }
#pragma unroll
    for (int i = 0; i < 8; i++) {
        int grow = row0 + ((i < 4) ? (4 * tr + i) : (64 + 4 * tr + i - 4));
        if (grow < NN) {
            float vals[8];
#pragma unroll
            for (int j = 0; j < 8; j++) {
                float v = accf[i][j] + bv[j];
                vals[j] = v;
                colsum[j] += v;
                colsq[j] += v * v;
            }
            *(float4*)&out[(long long)grow * HD + 4 * tc] =
                make_float4(vals[0], vals[1], vals[2], vals[3]);
            *(float4*)&out[(long long)grow * HD + 64 + 4 * tc] =
                make_float4(vals[4], vals[5], vals[6], vals[7]);
        }
    }
#pragma unroll
    for (int j = 0; j < 8; j++) {
        int c = (j < 4) ? (4 * tc + j) : (64 + 4 * tc + j - 4);
        atomicAdd(&s_sum[c], colsum[j]);
        atomicAdd(&s_sq[c], colsq[j]);
    }
    __syncthreads();
    if (tid < HD) {
        atomicAdd(&g_stats[tid], s_sum[tid]);
        atomicAdd(&g_stats[HD + tid], s_sq[tid]);
    }
}

// ---------------- finalize BN stats -> per-channel scale/shift ------------
__global__ void finalize_stats_kernel(const float* __restrict__ gamma,
                                      const float* __restrict__ beta)
{
    int c = threadIdx.x;
    const float inv = 1.0f / (float)NN;
    float mean = g_stats[c] * inv;
    float var = g_stats[HD + c] * inv - mean * mean;
    float sc = gamma[c] * rsqrtf(var + BN_EPS);
    g_scale[c] = sc;
    g_shift[c] = beta[c] - mean * sc;
}

// ---------------- GEMM2: out = relu?(relu(BN(x)) @ W + b) ----------------
__global__ __launch_bounds__(256) void gemm_bn_kernel(
    const float* __restrict__ xin, const float* __restrict__ W,
    const float* __restrict__ bias, float* __restrict__ out, int relu_out)
{
    __shared__ float a_s[64 * 128];
    __shared__ float w_s[64 * 128];
    int tid = threadIdx.x;
    int tr = tid >> 4;
    int tc = tid & 15;
    int row0 = blockIdx.x * 128;

    unsigned long long accp[4][8];
#pragma unroll
    for (int p = 0; p < 4; p++)
#pragma unroll
        for (int j = 0; j < 8; j++) accp[p][j] = 0ULL;

    for (int kc = 0; kc < 2; kc++) {
        int kbase = kc * 64;
        {
            int r = tid & 127;
            int half = tid >> 7;
            int grow = row0 + r;
#pragma unroll
            for (int p = 0; p < 8; p++) {
                int k = 4 * (half + 2 * p);
                float4 v = make_float4(0.f, 0.f, 0.f, 0.f);
                if (grow < NN) {
                    float4 xv = *(const float4*)&xin[(long long)grow * HD + kbase + k];
                    v.x = fmaxf(xv.x * g_scale[kbase + k + 0] + g_shift[kbase + k + 0], 0.f);
                    v.y = fmaxf(xv.y * g_scale[kbase + k + 1] + g_shift[kbase + k + 1], 0.f);
                    v.z = fmaxf(xv.z * g_scale[kbase + k + 2] + g_shift[kbase + k + 2], 0.f);
                    v.w = fmaxf(xv.w * g_scale[kbase + k + 3] + g_shift[kbase + k + 3], 0.f);
                }
                a_s[(k + 0) * 128 + r] = v.x;
                a_s[(k + 1) * 128 + r] = v.y;
                a_s[(k + 2) * 128 + r] = v.z;
                a_s[(k + 3) * 128 + r] = v.w;
            }
        }
        {
#pragma unroll
            for (int p = 0; p < 8; p++) {
                int idx = tid + p * 256;
                int k = idx >> 5;
                int q = idx & 31;
                *(float4*)&w_s[k * 128 + q * 4] =
                    *(const float4*)&W[(long long)(kbase + k) * HD + q * 4];
            }
        }
        __syncthreads();
#pragma unroll 4
        for (int k = 0; k < 64; k++) {
            ulonglong2 av0 = *(const ulonglong2*)(a_s + k * 128 + 4 * tr);
            ulonglong2 av1 = *(const ulonglong2*)(a_s + k * 128 + 64 + 4 * tr);
            float4 w0 = *(const float4*)(w_s + k * 128 + 4 * tc);
            float4 w1 = *(const float4*)(w_s + k * 128 + 64 + 4 * tc);
            unsigned long long ap[4] = {av0.x, av0.y, av1.x, av1.y};
            unsigned long long wp[8] = {
                bcast2(w0.x), bcast2(w0.y), bcast2(w0.z), bcast2(w0.w),
                bcast2(w1.x), bcast2(w1.y), bcast2(w1.z), bcast2(w1.w)};
#pragma unroll
            for (int p = 0; p < 4; p++)
#pragma unroll
                for (int j = 0; j < 8; j++)
                    ffma2(accp[p][j], ap[p], wp[j]);
        }
        __syncthreads();
    }

    float accf[8][8];
#pragma unroll
    for (int p = 0; p < 4; p++)
#pragma unroll
        for (int j = 0; j < 8; j++)
            unpack2(accp[p][j], accf[2 * p][j], accf[2 * p + 1][j]);

    float bv[8];
#pragma unroll
    for (int j = 0; j < 8; j++)
        bv[j] = bias[(j < 4) ? (4 * tc + j) : (64 + 4 * tc + j - 4)];

#pragma unroll
    for (int i = 0; i < 8; i++) {
        int grow = row0 + ((i < 4) ? (4 * tr + i) : (64 + 4 * tr + i - 4));
        if (grow < NN) {
            float vals[8];
#pragma unroll
            for (int j = 0; j < 8; j++) {
                float v = accf[i][j] + bv[j];
                if (relu_out) v = fmaxf(v, 0.f);
                vals[j] = v;
            }
            *(float4*)&out[(long long)grow * HD + 4 * tc] =
                make_float4(vals[0], vals[1], vals[2], vals[3]);
            *(float4*)&out[(long long)grow * HD + 64 + 4 * tc] =
                make_float4(vals[4], vals[5], vals[6], vals[7]);
        }
    }
}

// ---------------- per-graph readout (graph_ids sorted) --------------------
__global__ __launch_bounds__(256) void readout_kernel(const int* __restrict__ gids)
{
    int c = threadIdx.x;
    const float* h = (c < HD) ? g_enc0 : g_enc1;
    int cc = c & (HD - 1);
    int n0 = blockIdx.x * 128;
    int n1 = n0 + 128;
    if (n1 > NN) n1 = NN;
    int cur = gids[n0];
    float acc = 0.f;
    for (int n = n0; n < n1; n++) {
        int g = gids[n];
        if (g != cur) {
            atomicAdd(&g_hg[cur * 2 * HD + c], acc);
            acc = 0.f;
            cur = g;
        }
        acc += h[(long long)n * HD + cc];
    }
    atomicAdd(&g_hg[cur * 2 * HD + c], acc);
}

// ---------------- output MLP ----------------
__global__ void mlp1_kernel(const float* __restrict__ W, const float* __restrict__ b)
{
    __shared__ float row[2 * HD];
    int g = blockIdx.x, c = threadIdx.x;
    row[c] = g_hg[g * 2 * HD + c];
    row[c + HD] = g_hg[g * 2 * HD + c + HD];
    __syncthreads();
    float acc = b[c];
#pragma unroll 4
    for (int k = 0; k < 2 * HD; k++) acc = fmaf(row[k], W[k * HD + c], acc);
    g_m1[g * HD + c] = fmaxf(acc, 0.f);
}

__global__ void mlp2_kernel(const float* __restrict__ W, const float* __restrict__ b)
{
    __shared__ float row[HD];
    int g = blockIdx.x, c = threadIdx.x;
    row[c] = g_m1[g * HD + c];
    __syncthreads();
    float acc = b[c];
#pragma unroll 4
    for (int k = 0; k < HD; k++) acc = fmaf(row[k], W[k * HD + c], acc);
    g_m2[g * HD + c] = fmaxf(acc, 0.f);
}

__global__ void mlp3_kernel(const float* __restrict__ W, const float* __restrict__ b,
                            float* __restrict__ out)
{
    int g = threadIdx.x;
    if (g < NG) {
        float acc = b[0];
#pragma unroll 4
        for (int k = 0; k < HD; k++) acc = fmaf(g_m2[g * HD + k], W[k], acc);
        out[g] = acc;
    }
}

// ---------------- launch ----------------
extern "C" void kernel_launch(void* const* d_in, const int* in_sizes, int n_in,
                              void* d_out, int out_size)
{
    const float* feats = (const float*)d_in[0];
    const int* src = (const int*)d_in[1];
    const int* dst = (const int*)d_in[2];
    const int* gids = (const int*)d_in[3];
    const float* eps = (const float*)d_in[5];
    const float* Wa = (const float*)d_in[6];
    const float* ba = (const float*)d_in[7];
    const float* bng = (const float*)d_in[8];
    const float* bnb = (const float*)d_in[9];
    const float* Wb = (const float*)d_in[10];
    const float* bb = (const float*)d_in[11];
    const float* oW1 = (const float*)d_in[12];
    const float* ob1 = (const float*)d_in[13];
    const float* oW2 = (const float*)d_in[14];
    const float* ob2 = (const float*)d_in[15];
    const float* oW3 = (const float*)d_in[16];
    const float* ob3 = (const float*)d_in[17];
    float* out = (float*)d_out;

    float *aggp, *xp, *bufp, *e0p, *e1p, *statsp, *hgp;
    cudaGetSymbolAddress((void**)&aggp, g_agg);
    cudaGetSymbolAddress((void**)&xp, g_x);
    cudaGetSymbolAddress((void**)&bufp, g_buf);
    cudaGetSymbolAddress((void**)&e0p, g_enc0);
    cudaGetSymbolAddress((void**)&e1p, g_enc1);
    cudaGetSymbolAddress((void**)&statsp, g_stats);
    cudaGetSymbolAddress((void**)&hgp, g_hg);
    int *ei0p, *ei1p, *degp;
    cudaGetSymbolAddress((void**)&ei0p, g_eidx0);
    cudaGetSymbolAddress((void**)&ei1p, g_eidx1);
    cudaGetSymbolAddress((void**)&degp, g_deg);

    const int gemm_blocks = (NN + 127) / 128;        // 391
    const int edge_blocks = (NE + 255) / 256;        // 3125
    const int agg_blocks = (NN * 32 + 255) / 256;    // 6250

    for (int e = 0; e < 2; e++) {
        int* eidx = e ? ei1p : ei0p;
        cudaMemsetAsync(degp, 0, NN * sizeof(int));
        deg_kernel<<<edge_blocks, 256>>>(dst + (long long)e * NE);
        scan_kernel<<<1, 1024>>>();
        scatter_kernel<<<edge_blocks, 256>>>(src + (long long)e * NE,
                                             dst + (long long)e * NE, eidx);

        float* enc = e ? e1p : e0p;
        const float* hin = feats;
        for (int l = 0; l < 2; l++) {
            int wl = e * 2 + l;
            cudaMemsetAsync(statsp, 0, 2 * HD * sizeof(float));
            agg_csr_kernel<<<agg_blocks, 256>>>(hin, eidx, eps + wl, aggp);
            gemm_stats_kernel<<<gemm_blocks, 256>>>(
                aggp, Wa + (long long)wl * HD * HD, ba + wl * HD, xp);
            finalize_stats_kernel<<<1, HD>>>(bng + wl * HD, bnb + wl * HD);
            float* o = (l == 0) ? bufp : enc;
            gemm_bn_kernel<<<gemm_blocks, 256>>>(
                xp, Wb + (long long)wl * HD * HD, bb + wl * HD, o, (l == 0) ? 1 : 0);
            hin = bufp;
        }
    }

    cudaMemsetAsync(hgp, 0, NG * 2 * HD * sizeof(float));
    readout_kernel<<<(NN + 127) / 128, 256>>>(gids);
    mlp1_kernel<<<NG, HD>>>(oW1, ob1);
    mlp2_kernel<<<NG, HD>>>(oW2, ob2);
    mlp3_kernel<<<1, NG>>>(oW3, ob3, out);
}

// round 7
// speedup vs baseline: 2.3132x; 1.1308x over previous
#include <cuda_runtime.h>
#include <cuda_bf16.h>
#include <math.h>
#include <stdint.h>

#define NN 50000
#define NE 800000
#define NG 256
#define HD 128
#define BN_EPS 1e-5f

// ---------------- device scratch (no allocation allowed) ----------------
__device__ float g_agg[NN * HD];     // x-input = (1+eps)h + sum_nbr h
__device__ float g_x[NN * HD];
__device__ float g_buf[NN * HD];
__device__ float g_enc0[NN * HD];
__device__ float g_enc1[NN * HD];
__device__ float g_stats[2 * HD];
__device__ float g_scale[HD];
__device__ float g_shift[HD];
__device__ float g_hg[NG * 2 * HD];
__device__ float g_m1[NG * HD];
__device__ float g_m2[NG * HD];
__device__ __nv_bfloat16 g_wt_hi[HD * HD];   // W^T hi, [n][k]
__device__ __nv_bfloat16 g_wt_lo[HD * HD];   // W^T lo, [n][k]
// CSR scratch
__device__ int g_deg[NN];
__device__ int g_rowstart[NN + 1];
__device__ int g_cursor[NN];
__device__ int g_eidx0[NE];
__device__ int g_eidx1[NE];

// ---------------- CSR build ----------------
__global__ __launch_bounds__(256) void deg_kernel(const int* __restrict__ dst) {
    int i = blockIdx.x * blockDim.x + threadIdx.x;
    if (i < NE) atomicAdd(&g_deg[dst[i]], 1);
}

__global__ __launch_bounds__(1024) void scan_kernel() {
    __shared__ int ssum[1024];
    int t = threadIdx.x;
    const int CH = (NN + 1023) / 1024;
    int start = t * CH;
    int end = start + CH; if (end > NN) end = NN;
    if (start > NN) start = NN;
    int s = 0;
    for (int i = start; i < end; i++) s += g_deg[i];
    ssum[t] = s;
    __syncthreads();
    for (int off = 1; off < 1024; off <<= 1) {
        int v = (t >= off) ? ssum[t - off] : 0;
        __syncthreads();
        ssum[t] += v;
        __syncthreads();
    }
    int base = (t == 0) ? 0 : ssum[t - 1];
    for (int i = start; i < end; i++) {
        int d = g_deg[i];
        g_rowstart[i] = base;
        g_cursor[i] = base;
        base += d;
    }
    if (t == 1023) g_rowstart[NN] = base;
}

__global__ __launch_bounds__(256) void scatter_kernel(
    const int* __restrict__ src, const int* __restrict__ dst,
    int* __restrict__ eidx)
{
    int i = blockIdx.x * blockDim.x + threadIdx.x;
    if (i < NE) {
        int p = atomicAdd(&g_cursor[dst[i]], 1);
        eidx[p] = src[i];
    }
}

// -------- CSR aggregation: xout[n] = (1+eps)*h[n] + sum_{j in N(n)} h[j] ----
__global__ __launch_bounds__(256) void agg_csr_kernel(
    const float* __restrict__ h, const int* __restrict__ eidx,
    const float* __restrict__ eps_ptr, float* __restrict__ xout)
{
    int warp = (blockIdx.x * 256 + threadIdx.x) >> 5;
    int lane = threadIdx.x & 31;
    if (warp >= NN) return;
    int ro = g_rowstart[warp];
    int re = g_rowstart[warp + 1];
    float eps1 = 1.0f + eps_ptr[0];
    float4 hv = ((const float4*)h)[(long long)warp * 32 + lane];
    float4 acc = make_float4(eps1 * hv.x, eps1 * hv.y, eps1 * hv.z, eps1 * hv.w);
    int j = ro;
    for (; j + 4 <= re; j += 4) {
        int s0 = eidx[j], s1 = eidx[j + 1], s2 = eidx[j + 2], s3 = eidx[j + 3];
        float4 v0 = ((const float4*)h)[(long long)s0 * 32 + lane];
        float4 v1 = ((const float4*)h)[(long long)s1 * 32 + lane];
        float4 v2 = ((const float4*)h)[(long long)s2 * 32 + lane];
        float4 v3 = ((const float4*)h)[(long long)s3 * 32 + lane];
        acc.x += v0.x + v1.x + v2.x + v3.x;
        acc.y += v0.y + v1.y + v2.y + v3.y;
        acc.z += v0.z + v1.z + v2.z + v3.z;
        acc.w += v0.w + v1.w + v2.w + v3.w;
    }
    for (; j < re; j++) {
        int s = eidx[j];
        float4 v = ((const float4*)h)[(long long)s * 32 + lane];
        acc.x += v.x; acc.y += v.y; acc.z += v.z; acc.w += v.w;
    }
    ((float4*)xout)[(long long)warp * 32 + lane] = acc;
}

// ================= mma.sync bf16 GEMM machinery =================
// smem: A_hi[0,32K) A_lo[32K,64K) B_hi[64K,96K) B_lo[96K,128K)
#define GSM_TOTAL 131072

__device__ __forceinline__ uint32_t smem_u32(const void* p) {
    uint32_t a;
    asm("{ .reg .u64 t; cvta.to.shared.u64 t, %1; cvt.u32.u64 %0, t; }"
        : "=r"(a) : "l"(p));
    return a;
}
// swizzled byte offset of element (row, k) in a [128][128] bf16 tile
__device__ __forceinline__ uint32_t swz(int row, int k) {
    return (uint32_t)(row * 256 + ((((k >> 3) ^ (row & 7)) & 15) << 4) + (k & 7) * 2);
}
__device__ __forceinline__ unsigned int pack_bf2(float lo, float hi) {
    unsigned int r;
    asm("cvt.rn.bf16x2.f32 %0, %1, %2;" : "=r"(r) : "f"(hi), "f"(lo));
    return r;
}
__device__ __forceinline__ void ldm4(uint32_t* r, uint32_t addr) {
    asm volatile("ldmatrix.sync.aligned.m8n8.x4.shared.b16 {%0,%1,%2,%3}, [%4];"
        : "=r"(r[0]), "=r"(r[1]), "=r"(r[2]), "=r"(r[3]) : "r"(addr));
}
__device__ __forceinline__ void mma16816(float* d, const uint32_t* a,
                                         uint32_t b0, uint32_t b1) {
    asm volatile(
        "mma.sync.aligned.m16n8k16.row.col.f32.bf16.bf16.f32 "
        "{%0,%1,%2,%3}, {%4,%5,%6,%7}, {%8,%9}, {%0,%1,%2,%3};"
        : "+f"(d[0]), "+f"(d[1]), "+f"(d[2]), "+f"(d[3])
        : "r"(a[0]), "r"(a[1]), "r"(a[2]), "r"(a[3]), "r"(b0), "r"(b1));
}

// ---------------- W pre-convert: wt_hi/lo[n][k] = split(W[k][n]) ----------
__global__ __launch_bounds__(256) void wt_conv_kernel(const float* __restrict__ W) {
    int idx = blockIdx.x * 256 + threadIdx.x;
    if (idx < HD * HD) {
        int k = idx >> 7, n = idx & 127;
        float v = W[idx];
        __nv_bfloat16 h = __float2bfloat16(v);
        float r = v - __bfloat162float(h);
        g_wt_hi[n * HD + k] = h;
        g_wt_lo[n * HD + k] = __float2bfloat16(r);
    }
}

// ---------------- mma GEMM: out = act(xin') @ W + b ------------------
// xin' = xin (in_bn=0) or relu(xin*scale+shift) (in_bn=1); optional out relu.
__global__ __launch_bounds__(256, 1) void gemm_mma_kernel(
    const float* __restrict__ xin, const float* __restrict__ bias,
    float* __restrict__ out, int in_bn, int out_relu)
{
    extern __shared__ char smem[];
    __shared__ float sbias[HD];
    uint32_t sb = smem_u32(smem);
    int tid = threadIdx.x;
    int row0 = blockIdx.x * 128;

    if (tid < HD) sbias[tid] = bias[tid];

    // ---- stage A (hi/lo split, swizzled) ----
#pragma unroll
    for (int it = 0; it < 8; it++) {
        int idx = tid + it * 256;
        int row = idx >> 4;
        int k0 = (idx & 15) * 8;
        int grow = row0 + row;
        float f[8];
        if (grow < NN) {
            float4 v0 = *(const float4*)&xin[(long long)grow * HD + k0];
            float4 v1 = *(const float4*)&xin[(long long)grow * HD + k0 + 4];
            f[0] = v0.x; f[1] = v0.y; f[2] = v0.z; f[3] = v0.w;
            f[4] = v1.x; f[5] = v1.y; f[6] = v1.z; f[7] = v1.w;
            if (in_bn) {
#pragma unroll
                for (int i = 0; i < 8; i++)
                    f[i] = fmaxf(f[i] * g_scale[k0 + i] + g_shift[k0 + i], 0.f);
            }
        } else {
#pragma unroll
            for (int i = 0; i < 8; i++) f[i] = 0.f;
        }
        float hi[8], lo[8];
#pragma unroll
        for (int i = 0; i < 8; i++) {
            hi[i] = __bfloat162float(__float2bfloat16(f[i]));
            lo[i] = f[i] - hi[i];
        }
        uint4 hv = make_uint4(pack_bf2(hi[0], hi[1]), pack_bf2(hi[2], hi[3]),
                              pack_bf2(hi[4], hi[5]), pack_bf2(hi[6], hi[7]));
        uint4 lv = make_uint4(pack_bf2(lo[0], lo[1]), pack_bf2(lo[2], lo[3]),
                              pack_bf2(lo[4], lo[5]), pack_bf2(lo[6], lo[7]));
        uint32_t off = swz(row, k0);
        *(uint4*)(smem + off) = hv;
        *(uint4*)(smem + 32768 + off) = lv;
    }
    // ---- stage B (wt arrays already bf16 [n][k]) ----
#pragma unroll
    for (int it = 0; it < 8; it++) {
        int idx = tid + it * 256;
        int row = idx >> 4;
        int k0 = (idx & 15) * 8;
        uint4 hv = *(const uint4*)&g_wt_hi[row * HD + k0];
        uint4 lv = *(const uint4*)&g_wt_lo[row * HD + k0];
        uint32_t off = swz(row, k0);
        *(uint4*)(smem + 65536 + off) = hv;
        *(uint4*)(smem + 98304 + off) = lv;
    }
    __syncthreads();

    // ---- mainloop: warp w owns rows 16w..16w+15, all 128 cols ----
    int w = tid >> 5, l = tid & 31;
    float acc[16][4];
#pragma unroll
    for (int f = 0; f < 16; f++)
#pragma unroll
        for (int q = 0; q < 4; q++) acc[f][q] = 0.f;

    int rowA = 16 * w + ((l >> 3) & 1) * 8 + (l & 7);
    int aKoff = (l >> 4) * 8;
    int bRowL = ((l >> 4) << 3) + (l & 7);
    int bKoff = ((l >> 3) & 1) * 8;

#pragma unroll
    for (int ks = 0; ks < 8; ks++) {
        int k0 = ks * 16;
        uint32_t ah[4], al[4];
        uint32_t aaddr = sb + swz(rowA, k0 + aKoff);
        ldm4(ah, aaddr);
        ldm4(al, aaddr + 32768);
#pragma unroll
        for (int fg = 0; fg < 8; fg++) {
            uint32_t bh[4], bl[4];
            uint32_t baddr = sb + 65536 + swz(16 * fg + bRowL, k0 + bKoff);
            ldm4(bh, baddr);
            ldm4(bl, baddr + 32768);
            mma16816(acc[2 * fg], ah, bh[0], bh[1]);
            mma16816(acc[2 * fg], al, bh[0], bh[1]);
            mma16816(acc[2 * fg], ah, bl[0], bl[1]);
            mma16816(acc[2 * fg + 1], ah, bh[2], bh[3]);
            mma16816(acc[2 * fg + 1], al, bh[2], bh[3]);
            mma16816(acc[2 * fg + 1], ah, bl[2], bl[3]);
        }
    }

    // ---- epilogue: bias (+relu), store ----
    int g = l >> 2, t4 = l & 3;
    int r0 = row0 + 16 * w + g;
    int r1 = r0 + 8;
#pragma unroll
    for (int f = 0; f < 16; f++) {
        int n = 8 * f + 2 * t4;
        float b0 = sbias[n], b1 = sbias[n + 1];
        float o00 = acc[f][0] + b0, o01 = acc[f][1] + b1;
        float o10 = acc[f][2] + b0, o11 = acc[f][3] + b1;
        if (out_relu) {
            o00 = fmaxf(o00, 0.f); o01 = fmaxf(o01, 0.f);
            o10 = fmaxf(o10, 0.f); o11 = fmaxf(o11, 0.f);
        }
        if (r0 < NN) {
            float2 v = make_float2(o00, o01);
            *(float2*)&out[(long long)r0 * HD + n] = v;
        }
        if (r1 < NN) {
            float2 v = make_float2(o10, o11);
            *(float2*)&out[(long long)r1 * HD + n] = v;
        }
    }
}

// ---------------- BN column stats over g_x ----------------
__global__ __launch_bounds__(256) void stats_kernel(const float* __restrict__ x) {
    __shared__ float ss[256], sq[256];
    int tid = threadIdx.x;
    int col = tid & 127;
    int half = tid >> 7;
    int r0 = blockIdx.x * 128 + half * 64;
    float s = 0.f, q = 0.f;
    for (int i = 0; i < 64; i++) {
        int r = r0 + i;
        if (r < NN) {
            float v = x[(long long)r * HD + col];
            s += v;
            q += v * v;
        }
    }
    ss[tid] = s; sq[tid] = q;
    __syncthreads();
    if (half == 0) {
        s += ss[tid + 128];
        q += sq[tid + 128];
        atomicAdd(&g_stats[col], s);
        atomicAdd(&g_stats[HD + col], q);
    }
}

// ---------------- finalize BN stats -> per-channel scale/shift ------------
__global__ void finalize_stats_kernel(const float* __restrict__ gamma,
                                      const float* __restrict__ beta)
{
    int c = threadIdx.x;
    const float inv = 1.0f / (float)NN;
    float mean = g_stats[c] * inv;
    float var = g_stats[HD + c] * inv - mean * mean;
    float sc = gamma[c] * rsqrtf(var + BN_EPS);
    g_scale[c] = sc;
    g_shift[c] = beta[c] - mean * sc;
}

// ---------------- per-graph readout (graph_ids sorted) --------------------
__global__ __launch_bounds__(256) void readout_kernel(const int* __restrict__ gids)
{
    int c = threadIdx.x;
    const float* h = (c < HD) ? g_enc0 : g_enc1;
    int cc = c & (HD - 1);
    int n0 = blockIdx.x * 128;
    int n1 = n0 + 128;
    if (n1 > NN) n1 = NN;
    int cur = gids[n0];
    float acc = 0.f;
    for (int n = n0; n < n1; n++) {
        int g = gids[n];
        if (g != cur) {
            atomicAdd(&g_hg[cur * 2 * HD + c], acc);
            acc = 0.f;
            cur = g;
        }
        acc += h[(long long)n * HD + cc];
    }
    atomicAdd(&g_hg[cur * 2 * HD + c], acc);
}

// ---------------- output MLP ----------------
__global__ void mlp1_kernel(const float* __restrict__ W, const float* __restrict__ b)
{
    __shared__ float row[2 * HD];
    int g = blockIdx.x, c = threadIdx.x;
    row[c] = g_hg[g * 2 * HD + c];
    row[c + HD] = g_hg[g * 2 * HD + c + HD];
    __syncthreads();
    float acc = b[c];
#pragma unroll 4
    for (int k = 0; k < 2 * HD; k++) acc = fmaf(row[k], W[k * HD + c], acc);
    g_m1[g * HD + c] = fmaxf(acc, 0.f);
}

__global__ void mlp2_kernel(const float* __restrict__ W, const float* __restrict__ b)
{
    __shared__ float row[HD];
    int g = blockIdx.x, c = threadIdx.x;
    row[c] = g_m1[g * HD + c];
    __syncthreads();
    float acc = b[c];
#pragma unroll 4
    for (int k = 0; k < HD; k++) acc = fmaf(row[k], W[k * HD + c], acc);
    g_m2[g * HD + c] = fmaxf(acc, 0.f);
}

__global__ void mlp3_kernel(const float* __restrict__ W, const float* __restrict__ b,
                            float* __restrict__ out)
{
    int g = threadIdx.x;
    if (g < NG) {
        float acc = b[0];
#pragma unroll 4
        for (int k = 0; k < HD; k++) acc = fmaf(g_m2[g * HD + k], W[k], acc);
        out[g] = acc;
    }
}

// ---------------- launch ----------------
extern "C" void kernel_launch(void* const* d_in, const int* in_sizes, int n_in,
                              void* d_out, int out_size)
{
    const float* feats = (const float*)d_in[0];
    const int* src = (const int*)d_in[1];
    const int* dst = (const int*)d_in[2];
    const int* gids = (const int*)d_in[3];
    const float* eps = (const float*)d_in[5];
    const float* Wa = (const float*)d_in[6];
    const float* ba = (const float*)d_in[7];
    const float* bng = (const float*)d_in[8];
    const float* bnb = (const float*)d_in[9];
    const float* Wb = (const float*)d_in[10];
    const float* bb = (const float*)d_in[11];
    const float* oW1 = (const float*)d_in[12];
    const float* ob1 = (const float*)d_in[13];
    const float* oW2 = (const float*)d_in[14];
    const float* ob2 = (const float*)d_in[15];
    const float* oW3 = (const float*)d_in[16];
    const float* ob3 = (const float*)d_in[17];
    float* out = (float*)d_out;

    cudaFuncSetAttribute(gemm_mma_kernel,
                         cudaFuncAttributeMaxDynamicSharedMemorySize, GSM_TOTAL);

    float *aggp, *xp, *bufp, *e0p, *e1p, *statsp, *hgp;
    cudaGetSymbolAddress((void**)&aggp, g_agg);
    cudaGetSymbolAddress((void**)&xp, g_x);
    cudaGetSymbolAddress((void**)&bufp, g_buf);
    cudaGetSymbolAddress((void**)&e0p, g_enc0);
    cudaGetSymbolAddress((void**)&e1p, g_enc1);
    cudaGetSymbolAddress((void**)&statsp, g_stats);
    cudaGetSymbolAddress((void**)&hgp, g_hg);
    int *ei0p, *ei1p, *degp;
    cudaGetSymbolAddress((void**)&ei0p, g_eidx0);
    cudaGetSymbolAddress((void**)&ei1p, g_eidx1);
    cudaGetSymbolAddress((void**)&degp, g_deg);

    const int gemm_blocks = (NN + 127) / 128;        // 391
    const int edge_blocks = (NE + 255) / 256;        // 3125
    const int agg_blocks = (NN * 32 + 255) / 256;    // 6250

    for (int e = 0; e < 2; e++) {
        int* eidx = e ? ei1p : ei0p;
        cudaMemsetAsync(degp, 0, NN * sizeof(int));
        deg_kernel<<<edge_blocks, 256>>>(dst + (long long)e * NE);
        scan_kernel<<<1, 1024>>>();
        scatter_kernel<<<edge_blocks, 256>>>(src + (long long)e * NE,
                                             dst + (long long)e * NE, eidx);

        float* enc = e ? e1p : e0p;
        const float* hin = feats;
        for (int l = 0; l < 2; l++) {
            int wl = e * 2 + l;
            agg_csr_kernel<<<agg_blocks, 256>>>(hin, eidx, eps + wl, aggp);
            // GEMM1: x = agg @ Wa + ba
            wt_conv_kernel<<<64, 256>>>(Wa + (long long)wl * HD * HD);
            gemm_mma_kernel<<<gemm_blocks, 256, GSM_TOTAL>>>(
                aggp, ba + wl * HD, xp, 0, 0);
            // BN stats
            cudaMemsetAsync(statsp, 0, 2 * HD * sizeof(float));
            stats_kernel<<<gemm_blocks, 256>>>(xp);
            finalize_stats_kernel<<<1, HD>>>(bng + wl * HD, bnb + wl * HD);
            // GEMM2: out = act(relu(BN(x)) @ Wb + bb)
            float* o = (l == 0) ? bufp : enc;
            wt_conv_kernel<<<64, 256>>>(Wb + (long long)wl * HD * HD);
            gemm_mma_kernel<<<gemm_blocks, 256, GSM_TOTAL>>>(
                xp, bb + wl * HD, o, 1, (l == 0) ? 1 : 0);
            hin = bufp;
        }
    }

    cudaMemsetAsync(hgp, 0, NG * 2 * HD * sizeof(float));
    readout_kernel<<<(NN + 127) / 128, 256>>>(gids);
    mlp1_kernel<<<NG, HD>>>(oW1, ob1);
    mlp2_kernel<<<NG, HD>>>(oW2, ob2);
    mlp3_kernel<<<1, NG>>>(oW3, ob3, out);
}